// round 14
// baseline (speedup 1.0000x reference)
#include <cuda_runtime.h>
#include <cstdint>
#include <math.h>

#define VSZ 128
#define HW  (VSZ*VSZ)          // 16384
#define NB  4
#define NP  32
#define PE  16
#define NE  (NP*PE)            // 512 edges per batch
#define EPSF  1e-8f
#define BIGF  3.4e38f

// ---------------- scratch (static device globals; no allocation) ------------
// per edge: A = {v0x, v0y, v1y, ex}; Bv = {ey, ex*inv, ey*inv, ex/(ey+eps)}
// polys compacted: active polys occupy slots [0,nact), sentinels after.
__device__ float4 g_edges[NB*NE*2];      // 64 KB
__device__ int    g_nact[NB];
__device__ int    g_hv[NB];

// ---------------- kernel A: setup + compaction (4 blocks x 256) -------------
__global__ __launch_bounds__(256) void setup_kernel(
    const float* __restrict__ polygons,
    const float* __restrict__ attributes,
    const float* __restrict__ validity)
{
    __shared__ float2 shv[NP][PE];
    __shared__ int    s_act[NP], s_K[NP], s_slot[NP];

    int w = threadIdx.x >> 5;     // warp 0..7, handles polys 4w..4w+3
    int l = threadIdx.x & 31;
    int b = blockIdx.x;

    #pragma unroll
    for (int i = 0; i < 4; i++) {
        int n = w*4 + i;
        int poly = b*NP + n;
        const float* pp = polygons + (size_t)poly * PE * 2;
        float x = 0.0f, y = 0.0f;
        bool valid = false;
        if (l < PE) {
            x = pp[2*l + 0];
            y = pp[2*l + 1];
            valid = (x + y) != 0.0f;
        }
        unsigned vm = __ballot_sync(0xffffffffu, valid);
        int K   = __popc(vm);
        int pos = __popc(vm & ((1u << l) - 1u));
        if (valid) shv[n][pos] = make_float2(x, y);
        if (l == 0) {
            s_K[n]   = K;
            s_act[n] = (K >= 3 && validity[poly] >= 0.5f) ? 1 : 0;
        }
    }
    __syncthreads();

    if (w == 0) {   // warp 0: compaction slots via ballot over 32 poly flags
        int flag = s_act[l];
        unsigned am = __ballot_sync(0xffffffffu, flag != 0);
        int nact  = __popc(am);
        int below = __popc(am & ((1u << l) - 1u));
        s_slot[l] = flag ? below : (nact + (l - below));
        if (l == 0) {
            g_nact[b] = nact;
            float av = attributes[b];                  // (B,1)
            av = fminf(fmaxf(av, 0.0f), 1.0f);
            int hv = (int)rintf(av * (float)VSZ);      // half-even, like jnp.rint
            g_hv[b] = min(max(hv, 1), VSZ);
        }
    }
    __syncthreads();

    #pragma unroll
    for (int i = 0; i < 4; i++) {
        int n = w*4 + i;
        int slot = s_slot[n];
        int K    = s_K[n];
        bool act = s_act[n] != 0;
        if (l < PE) {
            float4 A, Bv;
            if (act && l < K) {
                float2 v0 = shv[n][l];
                float2 v1 = shv[n][(l + 1 == K) ? 0 : l + 1];
                float ex = v1.x - v0.x;
                float ey = v1.y - v0.y;
                float inv = 1.0f / (ex*ex + ey*ey + EPSF);
                A  = make_float4(v0.x, v0.y, v1.y, ex);
                Bv = make_float4(ey, ex*inv, ey*inv, ex / (ey + EPSF));
            } else {
                A  = make_float4(0.0f, 1e30f, 1e30f, 0.0f);   // sentinel
                Bv = make_float4(0.0f, 0.0f, 0.0f, 0.0f);
            }
            size_t eidx = ((size_t)(b*NP + slot) * PE + l) * 2;
            g_edges[eidx + 0] = A;
            g_edges[eidx + 1] = Bv;
        }
    }
}

// ------- kernel B: fused SDF + mask + depth broadcast (128 x 512) -----------
// Block = 4-row x 128-px tile (512 px). Thread = 4 adjacent px in one row x
// one quarter of the polygon slots -> each smem edge-load is reused by 4
// pixels (4x less smem return traffic). Partials combined via smem, depth
// broadcast via cp.async.bulk (2KB per depth slice).
__global__ __launch_bounds__(512, 1) void fused_kernel(float* __restrict__ out)
{
    __shared__ float4 sRE[4*NE];                   // {c1, ix_enc, vy, v0x}  32KB
    __shared__ float4 sEC[NE];                     // {ex, ey, ex*inv, 0}     8KB
    __shared__ __align__(16) float sS[4][512];     // per-quarter signed d^2   8KB
    __shared__ __align__(16) float s_cmb[512];     // combined tile            2KB
    __shared__ __align__(16) float s_zero[512];    // zero tile                2KB
    __shared__ int    s_nact, s_hv;

    int b    = blockIdx.x >> 5;       // 32 tiles per batch
    int tile = blockIdx.x & 31;       // 4-row tile within batch
    int t    = threadIdx.x;

    const float hstep = 1.0f / (float)(VSZ - 1);
    const float4* ge = g_edges + (size_t)b * NE * 2;

    // ---- phase 1: row-edge table (2048 entries, 4 per thread) ----
    #pragma unroll
    for (int k = 0; k < 4; k++) {
        int i    = t + 512*k;
        int rr   = i >> 9;            // row within block
        int eidx = i & (NE - 1);
        float4 A  = ge[eidx*2 + 0];   // v0x, v0y, v1y, ex
        float4 Bv = ge[eidx*2 + 1];   // ey, ex*inv, ey*inv, ex/(ey+eps)
        float py  = (float)(tile*4 + rr) * hstep;
        float vy  = py - A.y;
        bool  yc  = (A.y <= py) != (A.z <= py);
        float ix  = fmaf(Bv.w, vy, A.x);
        float c1  = fmaf(-A.x, Bv.y, vy * Bv.z);   // t = px*(ex*inv) + c1
        sRE[i] = make_float4(c1, yc ? ix : -BIGF, vy, A.x);
        if (k == 0)                    // rr==0 here; also fill edge constants
            sEC[eidx] = make_float4(A.w, Bv.x, Bv.y, 0.0f);
    }
    s_zero[t] = 0.0f;
    if (t == 0) { s_nact = g_nact[b]; s_hv = g_hv[b]; }
    __syncthreads();

    int g  = t & 127;                 // pixel group (4 px)
    int qd = t >> 7;                  // poly quarter
    int rr = g >> 5;                  // row within tile
    int pb = (g & 31) * 4;            // first px of this group
    int pl = rr * VSZ + pb;           // pixel index within the 512-px tile

    float px0 = (float)(pb    ) * hstep;
    float px1 = (float)(pb + 1) * hstep;
    float px2 = (float)(pb + 2) * hstep;
    float px3 = (float)(pb + 3) * hstep;
    const float4* REr = sRE + rr * NE;

    // min over this quarter's polys of signed d^2 for 4 pixels
    float S0 = BIGF, S1 = BIGF, S2 = BIGF, S3 = BIGF;
    int np4 = (s_nact + 3) >> 2;      // slots qd*np4+i, i<np4; sentinels safe
    for (int i = 0; i < np4; i++) {
        int slot = qd * np4 + i;
        const float4* Rp = REr + slot*PE;
        const float4* Ep = sEC + slot*PE;
        float m0 = BIGF, m1 = BIGF, m2 = BIGF, m3 = BIGF;
        unsigned c0 = 0u, c1c = 0u, c2 = 0u, c3 = 0u;
        #pragma unroll
        for (int e = 0; e < PE; e++) {
            float4 R = Rp[e];          // c1, ix_enc, vy, v0x (broadcast LDS)
            float4 E = Ep[e];          // ex, ey, ex*inv
            float q0 = __saturatef(fmaf(px0, E.z, R.x));
            float q1 = __saturatef(fmaf(px1, E.z, R.x));
            float q2 = __saturatef(fmaf(px2, E.z, R.x));
            float q3 = __saturatef(fmaf(px3, E.z, R.x));
            float u0 = px0 - R.w;
            float u1 = px1 - R.w;
            float u2 = px2 - R.w;
            float u3 = px3 - R.w;
            float dx0 = fmaf(-E.x, q0, u0), dy0 = fmaf(-E.y, q0, R.z);
            float dx1 = fmaf(-E.x, q1, u1), dy1 = fmaf(-E.y, q1, R.z);
            float dx2 = fmaf(-E.x, q2, u2), dy2 = fmaf(-E.y, q2, R.z);
            float dx3 = fmaf(-E.x, q3, u3), dy3 = fmaf(-E.y, q3, R.z);
            m0 = fminf(m0, fmaf(dy0, dy0, dx0*dx0));
            m1 = fminf(m1, fmaf(dy1, dy1, dx1*dx1));
            m2 = fminf(m2, fmaf(dy2, dy2, dx2*dx2));
            m3 = fminf(m3, fmaf(dy3, dy3, dx3*dx3));
            c0  ^= (R.y > px0) ? 1u : 0u;
            c1c ^= (R.y > px1) ? 1u : 0u;
            c2  ^= (R.y > px2) ? 1u : 0u;
            c3  ^= (R.y > px3) ? 1u : 0u;
        }
        S0 = fminf(S0, __uint_as_float(__float_as_uint(m0) ^ (c0  << 31)));
        S1 = fminf(S1, __uint_as_float(__float_as_uint(m1) ^ (c1c << 31)));
        S2 = fminf(S2, __uint_as_float(__float_as_uint(m2) ^ (c2  << 31)));
        S3 = fminf(S3, __uint_as_float(__float_as_uint(m3) ^ (c3  << 31)));
    }
    *reinterpret_cast<float4*>(&sS[qd][pl]) = make_float4(S0, S1, S2, S3);
    __syncthreads();

    // ---- combine quarters, sigmoid, stage ----
    {
        float S = fminf(fminf(sS[0][t], sS[1][t]), fminf(sS[2][t], sS[3][t]));
        float d   = sqrtf(fabsf(S));
        float sdf = (S < 0.0f) ? -d : d;
        s_cmb[t] = __fdividef(1.0f, 1.0f + __expf(100.0f * sdf));
    }
    __syncthreads();

    // ---- depth broadcast: 128 async bulk copies of 2KB ----
    if (t < VSZ) {
        asm volatile("fence.proxy.async.shared::cta;" ::: "memory");
        int dz = t;                                  // depth slice
        const float* srcp = (dz < s_hv) ? s_cmb : s_zero;
        unsigned int saddr;
        asm("{ .reg .u64 a; cvta.to.shared.u64 a, %1; cvt.u32.u64 %0, a; }"
            : "=r"(saddr) : "l"(srcp));
        float* gdst = out + ((size_t)b * VSZ + dz) * HW + tile * 512;
        asm volatile("cp.async.bulk.global.shared::cta.bulk_group [%0], [%1], %2;"
                     :: "l"(gdst), "r"(saddr), "r"(512u * 4u) : "memory");
        asm volatile("cp.async.bulk.commit_group;" ::: "memory");
        asm volatile("cp.async.bulk.wait_group 0;" ::: "memory");
    }
}

// ---------------- launch ----------------------------------------------------
extern "C" void kernel_launch(void* const* d_in, const int* in_sizes, int n_in,
                              void* d_out, int out_size)
{
    const float* polygons   = (const float*)d_in[0];   // (4,32,16,2)
    const float* attributes = (const float*)d_in[1];   // (4,1)
    const float* validity   = (const float*)d_in[2];   // (4,32)
    float* out = (float*)d_out;                        // (4,128,128,128)

    setup_kernel<<<NB, 256>>>(polygons, attributes, validity);
    fused_kernel<<<NB*32, 512>>>(out);
}